// round 1
// baseline (speedup 1.0000x reference)
#include <cuda_runtime.h>

#define NMAX 50000
#define RR 3
#define HH 64
#define CC 5

// ---------------- device scratch (no allocations allowed) ----------------
__device__ __align__(16) float g_hr[(size_t)RR * NMAX * HH];   // per-relation transformed feats
__device__ __align__(16) float g_bufA[(size_t)NMAX * HH];      // layer1 acc / h1
__device__ __align__(16) float g_bufB[(size_t)NMAX * HH];      // layer2 acc / h2
__device__ int   g_cnt[NMAX * RR];
__device__ float g_inv[NMAX * RR];
__device__ int   g_is64;

// ---------------- index-width detection (int64 vs int32) ----------------
// JAX without x64 silently downcasts the declared int64 indices to int32.
// For int64 little-endian values in [0, 50000), every odd 32-bit word is 0.
__global__ void detect_k(const int* __restrict__ w, int e) {
    __shared__ int nz;
    if (threadIdx.x == 0) nz = 0;
    __syncthreads();
    int npairs = e < 1024 ? e : 1024;   // reads 2*npairs int32 <= 2e words: safe either way
    int local = 0;
    for (int i = threadIdx.x; i < npairs; i += blockDim.x)
        if (w[2 * i + 1] != 0) local = 1;
    if (local) atomicExch(&nz, 1);
    __syncthreads();
    if (threadIdx.x == 0) g_is64 = (nz == 0) ? 1 : 0;
}

__device__ __forceinline__ int load_idx(const void* p, long long i) {
    if (g_is64) return (int)((const long long*)p)[i];
    return ((const int*)p)[i];
}

// ---------------- degree counts + reciprocals ----------------
__global__ void zero_cnt_k(int n3) {
    int i = blockIdx.x * blockDim.x + threadIdx.x;
    if (i < n3) g_cnt[i] = 0;
}

__global__ void count_k(const void* __restrict__ ei, const void* __restrict__ et, int e) {
    int i = blockIdx.x * blockDim.x + threadIdx.x;
    if (i < e) {
        int dst = load_idx(ei, (long long)e + i);
        int r   = load_idx(et, i);
        atomicAdd(&g_cnt[dst * RR + r], 1);
    }
}

__global__ void inv_k(int n3) {
    int i = blockIdx.x * blockDim.x + threadIdx.x;
    if (i < n3) {
        int c = g_cnt[i];
        g_inv[i] = 1.0f / (float)(c > 0 ? c : 1);
    }
}

// ---------------- fused 4-way GEMM: out = in @ W  (W in smem) ----------------
// blockIdx.y = m: m in [0,3) -> relation weight, out = g_hr[m];
//                 m == 3     -> root weight + bias, out = acc buffer.
__global__ __launch_bounds__(128) void gemm4_k(
    const float* __restrict__ xext,
    const float* __restrict__ Wrel,
    const float* __restrict__ root,
    const float* __restrict__ bias,
    int n, int layer)
{
    __shared__ __align__(16) float Ws[HH * HH];
    int m = blockIdx.y;
    const float* W = (m < RR) ? (Wrel + m * HH * HH) : root;
    int tid = threadIdx.x;
    for (int i = tid; i < HH * HH; i += 128) Ws[i] = W[i];
    __syncthreads();

    int row = blockIdx.x * 128 + tid;
    if (row >= n) return;

    const float* xin = (layer == 1) ? xext : g_bufA;
    const float4* x4 = (const float4*)(xin + (size_t)row * HH);

    float acc[HH];
    if (m < RR) {
        #pragma unroll
        for (int c = 0; c < HH; c++) acc[c] = 0.0f;
    } else {
        const float4* b4 = (const float4*)bias;
        #pragma unroll
        for (int j = 0; j < 16; j++) {
            float4 v = b4[j];
            acc[4 * j + 0] = v.x; acc[4 * j + 1] = v.y;
            acc[4 * j + 2] = v.z; acc[4 * j + 3] = v.w;
        }
    }

    #pragma unroll 4
    for (int k4 = 0; k4 < 16; k4++) {
        float4 xv = x4[k4];
        #pragma unroll
        for (int j = 0; j < 16; j++) {
            float4 w;
            w = *(const float4*)&Ws[(4 * k4 + 0) * HH + 4 * j];
            acc[4*j+0] += xv.x * w.x; acc[4*j+1] += xv.x * w.y;
            acc[4*j+2] += xv.x * w.z; acc[4*j+3] += xv.x * w.w;
            w = *(const float4*)&Ws[(4 * k4 + 1) * HH + 4 * j];
            acc[4*j+0] += xv.y * w.x; acc[4*j+1] += xv.y * w.y;
            acc[4*j+2] += xv.y * w.z; acc[4*j+3] += xv.y * w.w;
            w = *(const float4*)&Ws[(4 * k4 + 2) * HH + 4 * j];
            acc[4*j+0] += xv.z * w.x; acc[4*j+1] += xv.z * w.y;
            acc[4*j+2] += xv.z * w.z; acc[4*j+3] += xv.z * w.w;
            w = *(const float4*)&Ws[(4 * k4 + 3) * HH + 4 * j];
            acc[4*j+0] += xv.w * w.x; acc[4*j+1] += xv.w * w.y;
            acc[4*j+2] += xv.w * w.z; acc[4*j+3] += xv.w * w.w;
        }
    }

    float* out;
    if (m < RR) out = g_hr + ((size_t)m * n + row) * HH;
    else        out = ((layer == 1) ? g_bufA : g_bufB) + (size_t)row * HH;

    float4* o4 = (float4*)out;
    #pragma unroll
    for (int j = 0; j < 16; j++)
        o4[j] = make_float4(acc[4*j], acc[4*j+1], acc[4*j+2], acc[4*j+3]);
}

// ---------------- scatter-add aggregation: warp per edge ----------------
__global__ void scatter_k(const void* __restrict__ ei, const void* __restrict__ et,
                          int n, int e, int layer)
{
    int gt = blockIdx.x * blockDim.x + threadIdx.x;
    int w = gt >> 5;
    int lane = gt & 31;
    if (w >= e) return;

    int src = load_idx(ei, w);
    int dst = load_idx(ei, (long long)e + w);
    int r   = load_idx(et, w);
    float s = g_inv[dst * RR + r];

    const float* h = g_hr + ((size_t)r * n + src) * HH;
    float* acc = ((layer == 1) ? g_bufA : g_bufB) + (size_t)dst * HH;

    atomicAdd(&acc[lane],      h[lane]      * s);
    atomicAdd(&acc[lane + 32], h[lane + 32] * s);
}

// ---------------- ReLU in place ----------------
__global__ void relu_k(int total, int layer) {
    int i = blockIdx.x * blockDim.x + threadIdx.x;
    if (i < total) {
        float* b = (layer == 1) ? g_bufA : g_bufB;
        float v = b[i];
        b[i] = v > 0.0f ? v : 0.0f;
    }
}

// ---------------- classifier head: out = h2 @ Wc + bc ----------------
__global__ __launch_bounds__(128) void final_k(const float* __restrict__ Wc,
                                               const float* __restrict__ bc,
                                               float* __restrict__ out, int n)
{
    __shared__ float Ws[HH * CC];
    __shared__ float bs[CC];
    int tid = threadIdx.x;
    for (int i = tid; i < HH * CC; i += 128) Ws[i] = Wc[i];
    if (tid < CC) bs[tid] = bc[tid];
    __syncthreads();

    int row = blockIdx.x * 128 + tid;
    if (row >= n) return;

    float a[CC];
    #pragma unroll
    for (int c = 0; c < CC; c++) a[c] = bs[c];

    const float4* h4 = (const float4*)(g_bufB + (size_t)row * HH);
    #pragma unroll 4
    for (int k4 = 0; k4 < 16; k4++) {
        float4 v = h4[k4];
        #pragma unroll
        for (int c = 0; c < CC; c++) {
            a[c] += v.x * Ws[(4*k4+0)*CC + c]
                  + v.y * Ws[(4*k4+1)*CC + c]
                  + v.z * Ws[(4*k4+2)*CC + c]
                  + v.w * Ws[(4*k4+3)*CC + c];
        }
    }
    #pragma unroll
    for (int c = 0; c < CC; c++) out[(size_t)row * CC + c] = a[c];
}

// ---------------- launch ----------------
extern "C" void kernel_launch(void* const* d_in, const int* in_sizes, int n_in,
                              void* d_out, int out_size)
{
    const float* x     = (const float*)d_in[0];
    const float* W1    = (const float*)d_in[1];
    const float* root1 = (const float*)d_in[2];
    const float* b1    = (const float*)d_in[3];
    const float* W2    = (const float*)d_in[4];
    const float* root2 = (const float*)d_in[5];
    const float* b2    = (const float*)d_in[6];
    const float* Wc    = (const float*)d_in[7];
    const float* bc    = (const float*)d_in[8];
    const void*  ei    = d_in[9];
    const void*  et    = d_in[10];
    float* out = (float*)d_out;

    int n  = in_sizes[0] / HH;    // 50000
    int e  = in_sizes[10];        // 800000
    int n3 = n * RR;

    detect_k<<<1, 256>>>((const int*)ei, e);

    zero_cnt_k<<<(n3 + 255) / 256, 256>>>(n3);
    count_k<<<(e + 255) / 256, 256>>>(ei, et, e);
    inv_k<<<(n3 + 255) / 256, 256>>>(n3);

    dim3 gg((n + 127) / 128, 4);

    // layer 1
    gemm4_k<<<gg, 128>>>(x, W1, root1, b1, n, 1);
    scatter_k<<<(e * 32 + 255) / 256, 256>>>(ei, et, n, e, 1);
    relu_k<<<(n * HH + 255) / 256, 256>>>(n * HH, 1);

    // layer 2
    gemm4_k<<<gg, 128>>>(nullptr, W2, root2, b2, n, 2);
    scatter_k<<<(e * 32 + 255) / 256, 256>>>(ei, et, n, e, 2);
    relu_k<<<(n * HH + 255) / 256, 256>>>(n * HH, 2);

    // head
    final_k<<<(n + 127) / 128, 128>>>(Wc, bc, out, n);
}

// round 5
// speedup vs baseline: 1.6723x; 1.6723x over previous
#include <cuda_runtime.h>

#define NMAX 50000
#define EMAX 800000
#define RR 3
#define HH 64
#define CC 5
#define N3MAX (NMAX * RR)
#define SLICE ((size_t)NMAX * HH)   // 3,200,000 floats per slice

// ---------------- device scratch: keep TOTAL statics < 62 MiB ----------------
// g_pool layout (4 slices of N*64 floats = 51.2 MB):
//   slice 0..2 : per-relation aggregated means  (h2 output aliases slice 0)
//   slice 3    : h1 (layer-1 output)
__device__ __align__(16) float g_pool[4 * SLICE];
__device__ int   g_cnt[N3MAX];
__device__ int   g_cur[N3MAX];
__device__ int   g_offs[N3MAX + 1];
__device__ int   g_bsum[256];
__device__ float g_inv[N3MAX];
__device__ int   g_esrc[EMAX];
__device__ int   g_is64;

// ---------------- index-width detection (int64 vs int32) ----------------
__global__ void detect_k(const int* __restrict__ w, int e) {
    __shared__ int nz;
    if (threadIdx.x == 0) nz = 0;
    __syncthreads();
    int npairs = e < 1024 ? e : 1024;
    int local = 0;
    for (int i = threadIdx.x; i < npairs; i += blockDim.x)
        if (w[2 * i + 1] != 0) local = 1;
    if (local) atomicExch(&nz, 1);
    __syncthreads();
    if (threadIdx.x == 0) g_is64 = (nz == 0) ? 1 : 0;
}

__device__ __forceinline__ int load_idx(const void* p, long long i) {
    if (g_is64) return (int)((const long long*)p)[i];
    return ((const int*)p)[i];
}

// ---------------- CSR build ----------------
__global__ void zero_k(int n3) {
    int i = blockIdx.x * blockDim.x + threadIdx.x;
    if (i < n3) { g_cnt[i] = 0; g_cur[i] = 0; }
}

__global__ void count_k(const void* __restrict__ ei, const void* __restrict__ et, int e) {
    int i = blockIdx.x * blockDim.x + threadIdx.x;
    if (i < e) {
        int dst = load_idx(ei, (long long)e + i);
        int r   = load_idx(et, i);
        atomicAdd(&g_cnt[dst * RR + r], 1);
    }
}

__global__ void inv_k(int n3) {
    int i = blockIdx.x * blockDim.x + threadIdx.x;
    if (i < n3) {
        int c = g_cnt[i];
        g_inv[i] = 1.0f / (float)(c > 0 ? c : 1);
    }
}

// exclusive scan, pass 1: per-block (1024 elems) scan + block sums
__global__ __launch_bounds__(1024) void scan1_k(int n3) {
    __shared__ int sh[1024];
    int tid = threadIdx.x;
    int gi = blockIdx.x * 1024 + tid;
    int v = (gi < n3) ? g_cnt[gi] : 0;
    sh[tid] = v;
    __syncthreads();
    for (int off = 1; off < 1024; off <<= 1) {
        int t = (tid >= off) ? sh[tid - off] : 0;
        __syncthreads();
        sh[tid] += t;
        __syncthreads();
    }
    if (gi < n3) g_offs[gi] = sh[tid] - v;   // exclusive
    if (tid == 1023) g_bsum[blockIdx.x] = sh[1023];
}

// pass 2: scan the (<=256) block sums serially
__global__ void scan2_k(int nb) {
    if (threadIdx.x == 0 && blockIdx.x == 0) {
        int run = 0;
        for (int b = 0; b < nb; b++) {
            int t = g_bsum[b];
            g_bsum[b] = run;
            run += t;
        }
    }
}

// pass 3: add block offsets; set sentinel
__global__ void scan3_k(int n3, int e) {
    int gi = blockIdx.x * blockDim.x + threadIdx.x;
    if (gi < n3) g_offs[gi] += g_bsum[gi >> 10];
    else if (gi == n3) g_offs[n3] = e;
}

__global__ void fill_k(const void* __restrict__ ei, const void* __restrict__ et, int e) {
    int i = blockIdx.x * blockDim.x + threadIdx.x;
    if (i < e) {
        int src = load_idx(ei, i);
        int dst = load_idx(ei, (long long)e + i);
        int r   = load_idx(et, i);
        int w = dst * RR + r;
        int pos = g_offs[w] + atomicAdd(&g_cur[w], 1);
        g_esrc[pos] = src;
    }
}

// ---------------- atomic-free aggregation: warp per (dst, rel) segment ----------------
// layer==1: reads x (param). layer==2: reads h1 (pool slice 3).
// Writes agg means into pool slices 0..2.
__global__ void agg_k(const float* __restrict__ x, int n, int layer) {
    int gt = blockIdx.x * blockDim.x + threadIdx.x;
    int w = gt >> 5;
    int lane = gt & 31;
    int n3 = n * RR;
    if (w >= n3) return;

    const float* xin = (layer == 1) ? x : (g_pool + 3 * SLICE);

    int s = g_offs[w], t = g_offs[w + 1];
    float a0 = 0.f, a1 = 0.f, b0 = 0.f, b1 = 0.f;
    int i = s;
    for (; i + 1 < t; i += 2) {
        int s0 = g_esrc[i], s1 = g_esrc[i + 1];
        const float* p0 = xin + (size_t)s0 * HH;
        const float* p1 = xin + (size_t)s1 * HH;
        a0 += p0[lane]; a1 += p0[lane + 32];
        b0 += p1[lane]; b1 += p1[lane + 32];
    }
    if (i < t) {
        const float* p0 = xin + (size_t)g_esrc[i] * HH;
        a0 += p0[lane]; a1 += p0[lane + 32];
    }
    float sc = g_inv[w];
    int r = w % RR, dst = w / RR;
    float* o = g_pool + (size_t)r * SLICE + (size_t)dst * HH;
    o[lane]      = (a0 + b0) * sc;
    o[lane + 32] = (a1 + b1) * sc;
}

// ---------------- fused layer GEMM: out = relu(xin@root + sum_r agg[r]@W[r] + b) ----------------
// 128 threads/block, one row per thread, plain float accumulators (proven non-spilling idiom).
// layer==1: in = x (param), out = pool slice 3 (h1).
// layer==2: in = pool slice 3 (h1), out = pool slice 0 (h2; aliasing is safe:
//           each thread reads agg[0..2] of its own row before writing that row).
__global__ __launch_bounds__(128) void rgcn_gemm_k(
    const float* __restrict__ x,
    const float* __restrict__ Wrel,
    const float* __restrict__ root,
    const float* __restrict__ bias,
    int n, int layer)
{
    __shared__ __align__(16) float Ws[HH * HH];
    int tid = threadIdx.x;
    int row = blockIdx.x * 128 + tid;
    int crow = row < n ? row : 0;      // clamped for safe loads

    float acc[HH];
    {
        const float4* b4 = (const float4*)bias;
        #pragma unroll
        for (int j = 0; j < 16; j++) {
            float4 v = b4[j];
            acc[4 * j + 0] = v.x; acc[4 * j + 1] = v.y;
            acc[4 * j + 2] = v.z; acc[4 * j + 3] = v.w;
        }
    }

    const float* xin = (layer == 1) ? x : (g_pool + 3 * SLICE);

    for (int m = 0; m < 4; m++) {
        const float* W = (m == 0) ? root : (Wrel + (size_t)(m - 1) * HH * HH);
        __syncthreads();
        {
            const float4* w4 = (const float4*)W;
            float4* s4 = (float4*)Ws;
            for (int i = tid; i < HH * HH / 4; i += 128) s4[i] = w4[i];
        }
        __syncthreads();

        const float* in = (m == 0) ? xin : (g_pool + (size_t)(m - 1) * SLICE);
        const float4* x4 = (const float4*)(in + (size_t)crow * HH);

        #pragma unroll 4
        for (int k4 = 0; k4 < 16; k4++) {
            float4 xv = x4[k4];
            #pragma unroll
            for (int j = 0; j < 16; j++) {
                float4 w;
                w = *(const float4*)&Ws[(4 * k4 + 0) * HH + 4 * j];
                acc[4*j+0] += xv.x * w.x; acc[4*j+1] += xv.x * w.y;
                acc[4*j+2] += xv.x * w.z; acc[4*j+3] += xv.x * w.w;
                w = *(const float4*)&Ws[(4 * k4 + 1) * HH + 4 * j];
                acc[4*j+0] += xv.y * w.x; acc[4*j+1] += xv.y * w.y;
                acc[4*j+2] += xv.y * w.z; acc[4*j+3] += xv.y * w.w;
                w = *(const float4*)&Ws[(4 * k4 + 2) * HH + 4 * j];
                acc[4*j+0] += xv.z * w.x; acc[4*j+1] += xv.z * w.y;
                acc[4*j+2] += xv.z * w.z; acc[4*j+3] += xv.z * w.w;
                w = *(const float4*)&Ws[(4 * k4 + 3) * HH + 4 * j];
                acc[4*j+0] += xv.w * w.x; acc[4*j+1] += xv.w * w.y;
                acc[4*j+2] += xv.w * w.z; acc[4*j+3] += xv.w * w.w;
            }
        }
    }

    if (row < n) {
        float* outp = (layer == 1) ? (g_pool + 3 * SLICE) : g_pool;
        float4* o4 = (float4*)(outp + (size_t)row * HH);
        #pragma unroll
        for (int j = 0; j < 16; j++) {
            float a = acc[4*j]   > 0.f ? acc[4*j]   : 0.f;
            float b = acc[4*j+1] > 0.f ? acc[4*j+1] : 0.f;
            float c = acc[4*j+2] > 0.f ? acc[4*j+2] : 0.f;
            float d = acc[4*j+3] > 0.f ? acc[4*j+3] : 0.f;
            o4[j] = make_float4(a, b, c, d);
        }
    }
}

// ---------------- classifier head: out = h2 @ Wc + bc  (h2 = pool slice 0) ----------------
__global__ __launch_bounds__(128) void final_k(const float* __restrict__ Wc,
                                               const float* __restrict__ bc,
                                               float* __restrict__ out, int n)
{
    __shared__ float Ws[HH * CC];
    __shared__ float bs[CC];
    int tid = threadIdx.x;
    for (int i = tid; i < HH * CC; i += 128) Ws[i] = Wc[i];
    if (tid < CC) bs[tid] = bc[tid];
    __syncthreads();

    int row = blockIdx.x * 128 + tid;
    if (row >= n) return;

    float a[CC];
    #pragma unroll
    for (int c = 0; c < CC; c++) a[c] = bs[c];

    const float4* h4 = (const float4*)(g_pool + (size_t)row * HH);
    #pragma unroll 4
    for (int k4 = 0; k4 < 16; k4++) {
        float4 v = h4[k4];
        #pragma unroll
        for (int c = 0; c < CC; c++) {
            a[c] += v.x * Ws[(4 * k4 + 0) * CC + c]
                  + v.y * Ws[(4 * k4 + 1) * CC + c]
                  + v.z * Ws[(4 * k4 + 2) * CC + c]
                  + v.w * Ws[(4 * k4 + 3) * CC + c];
        }
    }
    #pragma unroll
    for (int c = 0; c < CC; c++) out[(size_t)row * CC + c] = a[c];
}

// ---------------- launch ----------------
extern "C" void kernel_launch(void* const* d_in, const int* in_sizes, int n_in,
                              void* d_out, int out_size)
{
    const float* x     = (const float*)d_in[0];
    const float* W1    = (const float*)d_in[1];
    const float* root1 = (const float*)d_in[2];
    const float* b1    = (const float*)d_in[3];
    const float* W2    = (const float*)d_in[4];
    const float* root2 = (const float*)d_in[5];
    const float* b2    = (const float*)d_in[6];
    const float* Wc    = (const float*)d_in[7];
    const float* bc    = (const float*)d_in[8];
    const void*  ei    = d_in[9];
    const void*  et    = d_in[10];
    float* out = (float*)d_out;

    int n  = in_sizes[0] / HH;     // 50000
    int e  = in_sizes[10];         // 800000
    int n3 = n * RR;
    int nb = (n3 + 1023) / 1024;

    detect_k<<<1, 256>>>((const int*)ei, e);

    // CSR build
    zero_k<<<(n3 + 255) / 256, 256>>>(n3);
    count_k<<<(e + 255) / 256, 256>>>(ei, et, e);
    inv_k<<<(n3 + 255) / 256, 256>>>(n3);
    scan1_k<<<nb, 1024>>>(n3);
    scan2_k<<<1, 32>>>(nb);
    scan3_k<<<(n3 + 1 + 255) / 256, 256>>>(n3, e);
    fill_k<<<(e + 255) / 256, 256>>>(ei, et, e);

    int aggBlocks  = (n3 * 32 + 255) / 256;
    int gemmBlocks = (n + 127) / 128;

    // layer 1: aggregate raw x per relation, then fused transform (+bias+relu)
    agg_k<<<aggBlocks, 256>>>(x, n, 1);
    rgcn_gemm_k<<<gemmBlocks, 128>>>(x, W1, root1, b1, n, 1);

    // layer 2
    agg_k<<<aggBlocks, 256>>>(x, n, 2);
    rgcn_gemm_k<<<gemmBlocks, 128>>>(x, W2, root2, b2, n, 2);

    // head
    final_k<<<(n + 127) / 128, 128>>>(Wc, bc, out, n);
}

// round 6
// speedup vs baseline: 1.6993x; 1.0161x over previous
#include <cuda_runtime.h>

#define NMAX 50000
#define EMAX 800000
#define RR 3
#define HH 64
#define CC 5
#define N3MAX (NMAX * RR)
#define SLICE ((size_t)NMAX * HH)   // 3,200,000 floats per slice

// ---------------- device scratch: keep TOTAL statics < 62 MiB ----------------
// g_pool layout (4 slices of N*64 floats = 51.2 MB):
//   slice 0..2 : per-relation aggregated means  (h2 output aliases slice 0)
//   slice 3    : h1 (layer-1 output)
__device__ __align__(16) float g_pool[4 * SLICE];
__device__ int   g_cnt[N3MAX];
__device__ int   g_cur[N3MAX];
__device__ int   g_offs[N3MAX + 1];
__device__ int   g_bsum[256];
__device__ float g_inv[N3MAX];
__device__ int   g_esrc[EMAX];
__device__ int   g_is64;

// ---------------- index-width detection (int64 vs int32) ----------------
__global__ void detect_k(const int* __restrict__ w, int e) {
    __shared__ int nz;
    if (threadIdx.x == 0) nz = 0;
    __syncthreads();
    int npairs = e < 1024 ? e : 1024;
    int local = 0;
    for (int i = threadIdx.x; i < npairs; i += blockDim.x)
        if (w[2 * i + 1] != 0) local = 1;
    if (local) atomicExch(&nz, 1);
    __syncthreads();
    if (threadIdx.x == 0) g_is64 = (nz == 0) ? 1 : 0;
}

__device__ __forceinline__ int load_idx(const void* p, long long i) {
    if (g_is64) return (int)((const long long*)p)[i];
    return ((const int*)p)[i];
}

// ---------------- CSR build ----------------
__global__ void zero_k(int n3) {
    int i = blockIdx.x * blockDim.x + threadIdx.x;
    if (i < n3) { g_cnt[i] = 0; g_cur[i] = 0; }
}

__global__ void count_k(const void* __restrict__ ei, const void* __restrict__ et, int e) {
    int i = blockIdx.x * blockDim.x + threadIdx.x;
    if (i < e) {
        int dst = load_idx(ei, (long long)e + i);
        int r   = load_idx(et, i);
        atomicAdd(&g_cnt[dst * RR + r], 1);
    }
}

__global__ void inv_k(int n3) {
    int i = blockIdx.x * blockDim.x + threadIdx.x;
    if (i < n3) {
        int c = g_cnt[i];
        g_inv[i] = 1.0f / (float)(c > 0 ? c : 1);
    }
}

// exclusive scan, pass 1: per-block (1024 elems) scan + block sums
__global__ __launch_bounds__(1024) void scan1_k(int n3) {
    __shared__ int sh[1024];
    int tid = threadIdx.x;
    int gi = blockIdx.x * 1024 + tid;
    int v = (gi < n3) ? g_cnt[gi] : 0;
    sh[tid] = v;
    __syncthreads();
    for (int off = 1; off < 1024; off <<= 1) {
        int t = (tid >= off) ? sh[tid - off] : 0;
        __syncthreads();
        sh[tid] += t;
        __syncthreads();
    }
    if (gi < n3) g_offs[gi] = sh[tid] - v;   // exclusive
    if (tid == 1023) g_bsum[blockIdx.x] = sh[1023];
}

// pass 2: scan the (<=256) block sums serially
__global__ void scan2_k(int nb) {
    if (threadIdx.x == 0 && blockIdx.x == 0) {
        int run = 0;
        for (int b = 0; b < nb; b++) {
            int t = g_bsum[b];
            g_bsum[b] = run;
            run += t;
        }
    }
}

// pass 3: add block offsets; set sentinel
__global__ void scan3_k(int n3, int e) {
    int gi = blockIdx.x * blockDim.x + threadIdx.x;
    if (gi < n3) g_offs[gi] += g_bsum[gi >> 10];
    else if (gi == n3) g_offs[n3] = e;
}

__global__ void fill_k(const void* __restrict__ ei, const void* __restrict__ et, int e) {
    int i = blockIdx.x * blockDim.x + threadIdx.x;
    if (i < e) {
        int src = load_idx(ei, i);
        int dst = load_idx(ei, (long long)e + i);
        int r   = load_idx(et, i);
        int w = dst * RR + r;
        int pos = g_offs[w] + atomicAdd(&g_cur[w], 1);
        g_esrc[pos] = src;
    }
}

// ---------------- atomic-free aggregation: warp per (dst, rel) segment ----------------
__global__ void agg_k(const float* __restrict__ x, int n, int layer) {
    int gt = blockIdx.x * blockDim.x + threadIdx.x;
    int w = gt >> 5;
    int lane = gt & 31;
    int n3 = n * RR;
    if (w >= n3) return;

    const float* xin = (layer == 1) ? x : (g_pool + 3 * SLICE);

    int s = g_offs[w], t = g_offs[w + 1];
    float a0 = 0.f, a1 = 0.f, b0 = 0.f, b1 = 0.f;
    int i = s;
    for (; i + 1 < t; i += 2) {
        int s0 = g_esrc[i], s1 = g_esrc[i + 1];
        const float* p0 = xin + (size_t)s0 * HH;
        const float* p1 = xin + (size_t)s1 * HH;
        a0 += p0[lane]; a1 += p0[lane + 32];
        b0 += p1[lane]; b1 += p1[lane + 32];
    }
    if (i < t) {
        const float* p0 = xin + (size_t)g_esrc[i] * HH;
        a0 += p0[lane]; a1 += p0[lane + 32];
    }
    float sc = g_inv[w];
    int r = w % RR, dst = w / RR;
    float* o = g_pool + (size_t)r * SLICE + (size_t)dst * HH;
    o[lane]      = (a0 + b0) * sc;
    o[lane + 32] = (a1 + b1) * sc;
}

// ---------------- packed f32x2 helpers (value semantics only) ----------------
__device__ __forceinline__ unsigned long long pack2(float x) {
    unsigned long long r;
    asm("mov.b64 %0, {%1, %1};" : "=l"(r) : "f"(x));
    return r;
}
__device__ __forceinline__ unsigned long long pack2two(float x, float y) {
    unsigned long long r;
    asm("mov.b64 %0, {%1, %2};" : "=l"(r) : "f"(x), "f"(y));
    return r;
}
__device__ __forceinline__ unsigned long long ffma2(unsigned long long a,
                                                    unsigned long long b,
                                                    unsigned long long c) {
    unsigned long long d;
    asm("fma.rn.f32x2 %0, %1, %2, %3;" : "=l"(d) : "l"(a), "l"(b), "l"(c));
    return d;
}
__device__ __forceinline__ float2 unpack2(unsigned long long v) {
    float2 f;
    asm("mov.b64 {%0, %1}, %2;" : "=f"(f.x), "=f"(f.y) : "l"(v));
    return f;
}

// ---------------- fused layer GEMM: out = relu(xin@root + sum_r agg[r]@W[r] + b) ----------------
// 128 threads/block, one row per thread, f32x2 packed accumulators (32 u64 = 64 regs).
__global__ __launch_bounds__(128) void rgcn_gemm_k(
    const float* __restrict__ x,
    const float* __restrict__ Wrel,
    const float* __restrict__ root,
    const float* __restrict__ bias,
    int n, int layer)
{
    __shared__ __align__(16) float Ws[HH * HH];
    int tid = threadIdx.x;
    int row = blockIdx.x * 128 + tid;
    int crow = row < n ? row : 0;      // clamped for safe loads

    unsigned long long acc[32];
    {
        const float2* b2 = (const float2*)bias;
        #pragma unroll
        for (int j = 0; j < 32; j++) {
            float2 b = b2[j];
            acc[j] = pack2two(b.x, b.y);
        }
    }

    const float* xin = (layer == 1) ? x : (g_pool + 3 * SLICE);

    for (int m = 0; m < 4; m++) {
        const float* W = (m == 0) ? root : (Wrel + (size_t)(m - 1) * HH * HH);
        __syncthreads();
        {
            const float4* w4 = (const float4*)W;
            float4* s4 = (float4*)Ws;
            for (int i = tid; i < HH * HH / 4; i += 128) s4[i] = w4[i];
        }
        __syncthreads();

        const float* in = (m == 0) ? xin : (g_pool + (size_t)(m - 1) * SLICE);
        const float4* x4 = (const float4*)(in + (size_t)crow * HH);

        #pragma unroll 2
        for (int k4 = 0; k4 < 16; k4++) {
            float4 v = x4[k4];
            #define GSTEP(E, KK)                                                   \
            {                                                                      \
                unsigned long long p = pack2(E);                                   \
                const ulonglong2* wr = (const ulonglong2*)&Ws[(4 * k4 + KK) * HH]; \
                _Pragma("unroll")                                                  \
                for (int j = 0; j < 16; j++) {                                     \
                    ulonglong2 w2 = wr[j];                                         \
                    acc[2 * j]     = ffma2(p, w2.x, acc[2 * j]);                   \
                    acc[2 * j + 1] = ffma2(p, w2.y, acc[2 * j + 1]);               \
                }                                                                  \
            }
            GSTEP(v.x, 0)
            GSTEP(v.y, 1)
            GSTEP(v.z, 2)
            GSTEP(v.w, 3)
            #undef GSTEP
        }
    }

    if (row < n) {
        float* outp = (layer == 1) ? (g_pool + 3 * SLICE) : g_pool;
        float4* o4 = (float4*)(outp + (size_t)row * HH);
        #pragma unroll
        for (int j = 0; j < 16; j++) {
            float2 lo = unpack2(acc[2 * j]);
            float2 hi = unpack2(acc[2 * j + 1]);
            float a = lo.x > 0.f ? lo.x : 0.f;
            float b = lo.y > 0.f ? lo.y : 0.f;
            float c = hi.x > 0.f ? hi.x : 0.f;
            float d = hi.y > 0.f ? hi.y : 0.f;
            o4[j] = make_float4(a, b, c, d);
        }
    }
}

// ---------------- classifier head: out = h2 @ Wc + bc  (h2 = pool slice 0) ----------------
__global__ __launch_bounds__(128) void final_k(const float* __restrict__ Wc,
                                               const float* __restrict__ bc,
                                               float* __restrict__ out, int n)
{
    __shared__ float Ws[HH * CC];
    __shared__ float bs[CC];
    int tid = threadIdx.x;
    for (int i = tid; i < HH * CC; i += 128) Ws[i] = Wc[i];
    if (tid < CC) bs[tid] = bc[tid];
    __syncthreads();

    int row = blockIdx.x * 128 + tid;
    if (row >= n) return;

    float a[CC];
    #pragma unroll
    for (int c = 0; c < CC; c++) a[c] = bs[c];

    const float4* h4 = (const float4*)(g_pool + (size_t)row * HH);
    #pragma unroll 4
    for (int k4 = 0; k4 < 16; k4++) {
        float4 v = h4[k4];
        #pragma unroll
        for (int c = 0; c < CC; c++) {
            a[c] += v.x * Ws[(4 * k4 + 0) * CC + c]
                  + v.y * Ws[(4 * k4 + 1) * CC + c]
                  + v.z * Ws[(4 * k4 + 2) * CC + c]
                  + v.w * Ws[(4 * k4 + 3) * CC + c];
        }
    }
    #pragma unroll
    for (int c = 0; c < CC; c++) out[(size_t)row * CC + c] = a[c];
}

// ---------------- launch ----------------
extern "C" void kernel_launch(void* const* d_in, const int* in_sizes, int n_in,
                              void* d_out, int out_size)
{
    const float* x     = (const float*)d_in[0];
    const float* W1    = (const float*)d_in[1];
    const float* root1 = (const float*)d_in[2];
    const float* b1    = (const float*)d_in[3];
    const float* W2    = (const float*)d_in[4];
    const float* root2 = (const float*)d_in[5];
    const float* b2    = (const float*)d_in[6];
    const float* Wc    = (const float*)d_in[7];
    const float* bc    = (const float*)d_in[8];
    const void*  ei    = d_in[9];
    const void*  et    = d_in[10];
    float* out = (float*)d_out;

    int n  = in_sizes[0] / HH;     // 50000
    int e  = in_sizes[10];         // 800000
    int n3 = n * RR;
    int nb = (n3 + 1023) / 1024;

    detect_k<<<1, 256>>>((const int*)ei, e);

    // CSR build
    zero_k<<<(n3 + 255) / 256, 256>>>(n3);
    count_k<<<(e + 255) / 256, 256>>>(ei, et, e);
    inv_k<<<(n3 + 255) / 256, 256>>>(n3);
    scan1_k<<<nb, 1024>>>(n3);
    scan2_k<<<1, 32>>>(nb);
    scan3_k<<<(n3 + 1 + 255) / 256, 256>>>(n3, e);
    fill_k<<<(e + 255) / 256, 256>>>(ei, et, e);

    int aggBlocks  = (n3 * 32 + 255) / 256;
    int gemmBlocks = (n + 127) / 128;

    // layer 1: aggregate raw x per relation, then fused transform (+bias+relu)
    agg_k<<<aggBlocks, 256>>>(x, n, 1);
    rgcn_gemm_k<<<gemmBlocks, 128>>>(x, W1, root1, b1, n, 1);

    // layer 2
    agg_k<<<aggBlocks, 256>>>(x, n, 2);
    rgcn_gemm_k<<<gemmBlocks, 128>>>(x, W2, root2, b2, n, 2);

    // head
    final_k<<<(n + 127) / 128, 128>>>(Wc, bc, out, n);
}